// round 1
// baseline (speedup 1.0000x reference)
#include <cuda_runtime.h>

// Problem constants
#define B_    16
#define CC    256
#define HH    64
#define WW    64
#define HW    4096            // H*W
#define NTOK  65536           // B*H*W
#define NE    1024            // codebook entries
#define D     256             // e_dim
#define ZQ_ELEMS (NTOK * CC)  // 16777216
#define LOSS_OFF ZQ_ELEMS
#define CLS_OFF  (ZQ_ELEMS + 1)
#define IDX_OFF  (ZQ_ELEMS + 2)

// Tiling for the fused GEMM+argmin
#define TM 128   // tokens per block
#define TN 64    // codes per code-tile
#define KB 32    // k-chunk for codebook staging
#define GRID_C 2048

// Scratch (no allocations allowed)
__device__ int   g_idx[NTOK];
__device__ float g_cnorm[NE];
__device__ float g_partial[GRID_C];

// ---------------------------------------------------------------------------
// Kernel 1: per-code squared norms (warp per row)
// ---------------------------------------------------------------------------
__global__ void __launch_bounds__(256) cnorm_kernel(const float* __restrict__ cb) {
    int row  = blockIdx.x * 8 + (threadIdx.x >> 5);
    int lane = threadIdx.x & 31;
    const float* p = cb + (size_t)row * D;
    float s = 0.f;
    for (int k = lane; k < D; k += 32) { float v = p[k]; s = fmaf(v, v, s); }
    #pragma unroll
    for (int o = 16; o; o >>= 1) s += __shfl_xor_sync(0xffffffffu, s, o);
    if (lane == 0) g_cnorm[row] = s;
}

// ---------------------------------------------------------------------------
// Kernel 2: fused distance GEMM + argmin.
// Block = 256 threads (16x16). Each block: 128 consecutive tokens vs all 1024
// codes. Full z tile resident in shared (read from HBM once); codebook tiles
// streamed (L2-hot). Per-thread register tile: 8 tokens x 4 codes.
// Shared layout (floats):
//   As   [D][TM]          = 32768
//   Bs   [KB][TN+1]       =  2080
//   cnS  [NE]             =  1024
//   rV   [TM][17]         =  2176
//   rI   [TM][17]         =  2176
// total 40224 floats = 160896 bytes (dynamic)
// ---------------------------------------------------------------------------
#define ARGMIN_SMEM_FLOATS (D*TM + KB*(TN+1) + NE + TM*17 + TM*17)
#define ARGMIN_SMEM_BYTES  (ARGMIN_SMEM_FLOATS * 4)

__global__ void __launch_bounds__(256) argmin_kernel(const float* __restrict__ z,
                                                     const float* __restrict__ cb,
                                                     float* __restrict__ dout) {
    extern __shared__ float smem[];
    float* As  = smem;                       // [D][TM]
    float* Bs  = As  + D * TM;               // [KB][TN+1]
    float* cnS = Bs  + KB * (TN + 1);        // [NE]
    float* rV  = cnS + NE;                   // [TM][17]
    float* rI  = rV  + TM * 17;              // [TM][17]

    const int tid = threadIdx.x;
    const int tx  = tid & 15;   // code lane
    const int ty  = tid >> 4;   // token lane

    const int n0  = blockIdx.x * TM;         // 4096 % 128 == 0 -> tile never crosses b
    const int b   = n0 / HW;
    const int rem = n0 % HW;
    const float* zbase = z + (size_t)b * CC * HW + rem;

    // Load z tile: As[k][t] = z[b, k, rem+t]  (coalesced across t)
    for (int i = tid; i < D * TM; i += 256) {
        int k = i >> 7;          // / TM
        int t = i & (TM - 1);
        As[k * TM + t] = zbase[(size_t)k * HW + t];
    }
    // Stage code norms
    for (int i = tid; i < NE; i += 256) cnS[i] = g_cnorm[i];

    float bestV[8];
    int   bestI[8];
    #pragma unroll
    for (int r = 0; r < 8; r++) { bestV[r] = 3.4e38f; bestI[r] = 0; }

    for (int j0 = 0; j0 < NE; j0 += TN) {
        float acc[8][4];
        #pragma unroll
        for (int r = 0; r < 8; r++)
            #pragma unroll
            for (int c = 0; c < 4; c++) acc[r][c] = 0.f;

        for (int k0 = 0; k0 < D; k0 += KB) {
            __syncthreads();
            // Bs[kk][j] = cb[(j0+j)*D + k0+kk]  (coalesced along kk)
            for (int i = tid; i < KB * TN; i += 256) {
                int j  = i >> 5;       // / KB
                int kk = i & (KB - 1);
                Bs[kk * (TN + 1) + j] = cb[(size_t)(j0 + j) * D + k0 + kk];
            }
            __syncthreads();

            #pragma unroll
            for (int kk = 0; kk < KB; kk++) {
                const float* Ar = As + (k0 + kk) * TM;
                const float* Br = Bs + kk * (TN + 1);
                float a[8], bb[4];
                #pragma unroll
                for (int r = 0; r < 8; r++) a[r] = Ar[ty + 16 * r];
                #pragma unroll
                for (int c = 0; c < 4; c++) bb[c] = Br[tx + 16 * c];
                #pragma unroll
                for (int r = 0; r < 8; r++)
                    #pragma unroll
                    for (int c = 0; c < 4; c++)
                        acc[r][c] = fmaf(a[r], bb[c], acc[r][c]);
            }
        }

        // Update per-thread running argmin (||c||^2 - 2 z.c); j ascending within
        // thread, so strict < keeps the first (lowest-index) minimum.
        #pragma unroll
        for (int c = 0; c < 4; c++) {
            int j = j0 + tx + 16 * c;
            float cn = cnS[j];
            #pragma unroll
            for (int r = 0; r < 8; r++) {
                float v = fmaf(-2.f, acc[r][c], cn);
                if (v < bestV[r] || (v == bestV[r] && j < bestI[r])) {
                    bestV[r] = v; bestI[r] = j;
                }
            }
        }
    }

    // Cross-thread reduction: token t owned by 16 threads (tx lanes)
    __syncthreads();
    #pragma unroll
    for (int r = 0; r < 8; r++) {
        int t = ty + 16 * r;
        rV[t * 17 + tx] = bestV[r];
        rI[t * 17 + tx] = __int_as_float(bestI[r]);
    }
    __syncthreads();
    if (tid < TM) {
        int t = tid;
        float bv = rV[t * 17];
        int   bi = __float_as_int(rI[t * 17]);
        #pragma unroll
        for (int x = 1; x < 16; x++) {
            float v = rV[t * 17 + x];
            int   i = __float_as_int(rI[t * 17 + x]);
            if (v < bv || (v == bv && i < bi)) { bv = v; bi = i; }
        }
        int n = n0 + t;
        g_idx[n] = bi;
        dout[IDX_OFF + n] = (float)bi;   // indices output [B,1,H,W] == token order
    }
}

// ---------------------------------------------------------------------------
// Kernel 3: gather z_q, straight-through output z + (z_q - z), partial loss.
// i linear over [b,c,h,w]: i = (b*C+c)*HW + hw ; token n = b*HW + hw.
// ---------------------------------------------------------------------------
__global__ void __launch_bounds__(256) gather_kernel(const float* __restrict__ z,
                                                     const float* __restrict__ cb,
                                                     float* __restrict__ dout) {
    float s = 0.f;
    const long long total  = (long long)ZQ_ELEMS;
    const long long stride = (long long)gridDim.x * 256;
    for (long long i = (long long)blockIdx.x * 256 + threadIdx.x; i < total; i += stride) {
        int hw = (int)(i & (HW - 1));
        int bc = (int)(i >> 12);          // / HW
        int b  = bc >> 8;                 // / C
        int c  = bc & (CC - 1);
        int n  = b * HW + hw;
        int idx = g_idx[n];
        float zq = cb[(size_t)idx * D + c];
        float zv = z[i];
        float d  = zq - zv;
        dout[i]  = zv + d;                // exact replication of z + sg(z_q - z)
        s = fmaf(d, d, s);
    }
    // deterministic per-block sum
    #pragma unroll
    for (int o = 16; o; o >>= 1) s += __shfl_xor_sync(0xffffffffu, s, o);
    __shared__ float ws[8];
    if ((threadIdx.x & 31) == 0) ws[threadIdx.x >> 5] = s;
    __syncthreads();
    if (threadIdx.x < 8) {
        float v = ws[threadIdx.x];
        #pragma unroll
        for (int o = 4; o; o >>= 1) v += __shfl_xor_sync(0xffu, v, o);
        if (threadIdx.x == 0) g_partial[blockIdx.x] = v;
    }
}

// ---------------------------------------------------------------------------
// Kernel 4: fixed-order final reduction -> deterministic scalars
// ---------------------------------------------------------------------------
__global__ void __launch_bounds__(256) finalize_kernel(float* __restrict__ dout) {
    __shared__ float sh[256];
    float s = 0.f;
    for (int i = threadIdx.x; i < GRID_C; i += 256) s += g_partial[i];
    sh[threadIdx.x] = s;
    __syncthreads();
    for (int o = 128; o; o >>= 1) {
        if (threadIdx.x < o) sh[threadIdx.x] += sh[threadIdx.x + o];
        __syncthreads();
    }
    if (threadIdx.x == 0) {
        // codebook_loss = q_latent + e_latent = 2 * mean((z_q - z)^2)
        dout[LOSS_OFF] = sh[0] * (2.0f / (float)ZQ_ELEMS);
        dout[CLS_OFF]  = 0.0f;
    }
}

// ---------------------------------------------------------------------------
extern "C" void kernel_launch(void* const* d_in, const int* in_sizes, int n_in,
                              void* d_out, int out_size) {
    const float* z  = (const float*)d_in[0];   // [B,C,H,W] fp32
    const float* cb = (const float*)d_in[1];   // [NE, D]   fp32
    float* out = (float*)d_out;

    cudaFuncSetAttribute(argmin_kernel,
                         cudaFuncAttributeMaxDynamicSharedMemorySize,
                         ARGMIN_SMEM_BYTES);

    cnorm_kernel <<<NE / 8, 256>>>(cb);
    argmin_kernel<<<NTOK / TM, 256, ARGMIN_SMEM_BYTES>>>(z, cb, out);
    gather_kernel<<<GRID_C, 256>>>(z, cb, out);
    finalize_kernel<<<1, 256>>>(out);
}

// round 2
// speedup vs baseline: 1.3186x; 1.3186x over previous
#include <cuda_runtime.h>

// Problem constants
#define B_    16
#define CC    256
#define HH    64
#define WW    64
#define HW    4096            // H*W
#define NTOK  65536           // B*H*W
#define NE    1024            // codebook entries
#define D     256             // e_dim
#define ZQ_ELEMS (NTOK * CC)  // 16777216
#define LOSS_OFF ZQ_ELEMS
#define CLS_OFF  (ZQ_ELEMS + 1)
#define IDX_OFF  (ZQ_ELEMS + 2)

// Tiling for the fused GEMM+argmin
#define TM 128       // tokens per block
#define TN 64        // codes per j-tile
#define KB 64        // k-chunk
#define NCHUNK 64    // (NE/TN) * (D/KB) = 16 * 4
#define BPITCH 65    // ull pitch of Bs rows (odd -> conflict-free)
#define BUFU (KB * BPITCH)
#define GRID_C 2048

typedef unsigned long long ull;

// Scratch (no allocations allowed)
__device__ int   g_idx[NTOK];
__device__ float g_cnorm[NE];
__device__ float g_partial[GRID_C];

// ---------------------------------------------------------------------------
// packed fp32x2 helpers (Blackwell full-rate fp32 path)
// ---------------------------------------------------------------------------
__device__ __forceinline__ ull pack2(float x) {
    ull r; asm("mov.b64 %0, {%1, %1};" : "=l"(r) : "f"(x)); return r;
}
__device__ __forceinline__ void fma2(ull& d, ull a, ull b) {
    asm("fma.rn.f32x2 %0, %1, %2, %0;" : "+l"(d) : "l"(a), "l"(b));
}
__device__ __forceinline__ void unpack2(ull v, float& lo, float& hi) {
    asm("mov.b64 {%0, %1}, %2;" : "=f"(lo), "=f"(hi) : "l"(v));
}

// ---------------------------------------------------------------------------
// Kernel 1: per-code squared norms (warp per row)
// ---------------------------------------------------------------------------
__global__ void __launch_bounds__(256) cnorm_kernel(const float* __restrict__ cb) {
    int row  = blockIdx.x * 8 + (threadIdx.x >> 5);
    int lane = threadIdx.x & 31;
    const float* p = cb + (size_t)row * D;
    float s = 0.f;
    for (int k = lane; k < D; k += 32) { float v = p[k]; s = fmaf(v, v, s); }
    #pragma unroll
    for (int o = 16; o; o >>= 1) s += __shfl_xor_sync(0xffffffffu, s, o);
    if (lane == 0) g_cnorm[row] = s;
}

// ---------------------------------------------------------------------------
// Kernel 2: fused distance GEMM + argmin, packed f32x2 math.
// Block = 256 threads (tx = code lane 0..15, ty = token group 0..15).
// Per thread: 8 tokens (4 packed pairs) x 4 codes = 16 ull accumulators.
// Full z tile [D][TM] resident in shared; codebook staged in double-buffered
// [KB][TN] ull chunks with each value DUPLICATED into both 32-bit halves so
// the inner loop needs no pack instructions.
// Smem bytes: As 131072 + Bs2 66560 + cn 4096 + rV 8704 + rI 8704 = 219136
// ---------------------------------------------------------------------------
#define ARGMIN_SMEM_BYTES (131072 + 2*BUFU*8 + NE*4 + TM*17*4 + TM*17*4)

__device__ __forceinline__ void ldg_chunk(const float* __restrict__ cb, int g,
                                          int tid, float4* st) {
    int j0 = (g >> 2) * TN;
    int k0 = (g & 3) * KB;
    #pragma unroll
    for (int l = 0; l < 4; l++) {
        int fid = tid + l * 256;
        int j   = fid >> 4;
        int kk  = (fid & 15) * 4;
        st[l] = *(const float4*)(cb + (size_t)(j0 + j) * D + k0 + kk);
    }
}
__device__ __forceinline__ void sts_chunk(ull* buf, int tid, const float4* st) {
    #pragma unroll
    for (int l = 0; l < 4; l++) {
        int fid = tid + l * 256;
        int j   = fid >> 4;
        int kk  = (fid & 15) * 4;
        buf[(kk + 0) * BPITCH + j] = pack2(st[l].x);
        buf[(kk + 1) * BPITCH + j] = pack2(st[l].y);
        buf[(kk + 2) * BPITCH + j] = pack2(st[l].z);
        buf[(kk + 3) * BPITCH + j] = pack2(st[l].w);
    }
}

__global__ void __launch_bounds__(256) argmin_kernel(const float* __restrict__ z,
                                                     const float* __restrict__ cb,
                                                     float* __restrict__ dout) {
    extern __shared__ float smem[];
    float* As  = smem;                                   // [D][TM]
    ull*   Bs2 = (ull*)(smem + D * TM);                  // [2][KB][BPITCH]
    float* cnS = (float*)(Bs2 + 2 * BUFU);               // [NE]
    float* rV  = cnS + NE;                               // [TM][17]
    float* rI  = rV + TM * 17;                           // [TM][17]

    const int tid = threadIdx.x;
    const int tx  = tid & 15;
    const int ty  = tid >> 4;

    const int n0  = blockIdx.x * TM;     // 4096 % 128 == 0 -> never crosses b
    const int b   = n0 / HW;
    const int rem = n0 % HW;
    const float* zbase = z + (size_t)b * CC * HW + rem;

    // Load z tile: As[k][t] = z[b, k, rem+t]   (coalesced across t)
    for (int i = tid; i < D * TM; i += 256) {
        int k = i >> 7;
        int t = i & (TM - 1);
        As[k * TM + t] = zbase[(size_t)k * HW + t];
    }
    for (int i = tid; i < NE; i += 256) cnS[i] = g_cnorm[i];

    // prefetch chunk 0
    {
        float4 st[4];
        ldg_chunk(cb, 0, tid, st);
        sts_chunk(Bs2, tid, st);
    }
    __syncthreads();

    float bestV[8];
    int   bestI[8];
    #pragma unroll
    for (int r = 0; r < 8; r++) { bestV[r] = 3.4e38f; bestI[r] = 0; }

    ull acc[4][4];
    const ull* Ap   = (const ull*)As;
    const int  aoff = ty * 4;            // token pair base in ull units

    for (int g = 0; g < NCHUNK; g++) {
        const int ck = g & 3;
        if (ck == 0) {
            #pragma unroll
            for (int p = 0; p < 4; p++)
                #pragma unroll
                for (int c = 0; c < 4; c++) acc[p][c] = 0ull;
        }
        float4 st[4];
        if (g < NCHUNK - 1) ldg_chunk(cb, g + 1, tid, st);

        const ull* Bb   = Bs2 + (g & 1) * BUFU;
        const int kbase = ck * KB;
        #pragma unroll 16
        for (int kk = 0; kk < KB; kk++) {
            const ull* ar = Ap + (kbase + kk) * (TM / 2) + aoff;
            ull a0 = ar[0], a1 = ar[1], a2 = ar[2], a3 = ar[3];
            const ull* br = Bb + kk * BPITCH + tx;
            ull b0 = br[0], b1 = br[16], b2 = br[32], b3 = br[48];
            fma2(acc[0][0], a0, b0); fma2(acc[1][0], a1, b0);
            fma2(acc[2][0], a2, b0); fma2(acc[3][0], a3, b0);
            fma2(acc[0][1], a0, b1); fma2(acc[1][1], a1, b1);
            fma2(acc[2][1], a2, b1); fma2(acc[3][1], a3, b1);
            fma2(acc[0][2], a0, b2); fma2(acc[1][2], a1, b2);
            fma2(acc[2][2], a2, b2); fma2(acc[3][2], a3, b2);
            fma2(acc[0][3], a0, b3); fma2(acc[1][3], a1, b3);
            fma2(acc[2][3], a2, b3); fma2(acc[3][3], a3, b3);
        }
        if (g < NCHUNK - 1) sts_chunk(Bs2 + ((g + 1) & 1) * BUFU, tid, st);
        __syncthreads();

        if (ck == 3) {
            const int j0 = (g >> 2) * TN;
            #pragma unroll
            for (int c = 0; c < 4; c++) {
                int j = j0 + tx + 16 * c;
                float cn = cnS[j];
                #pragma unroll
                for (int p = 0; p < 4; p++) {
                    float lo, hi;
                    unpack2(acc[p][c], lo, hi);
                    float v0 = fmaf(-2.f, lo, cn);
                    float v1 = fmaf(-2.f, hi, cn);
                    // j strictly ascending per token -> strict < keeps lowest idx
                    if (v0 < bestV[2 * p])     { bestV[2 * p]     = v0; bestI[2 * p]     = j; }
                    if (v1 < bestV[2 * p + 1]) { bestV[2 * p + 1] = v1; bestI[2 * p + 1] = j; }
                }
            }
        }
    }

    // Cross-thread reduction: token t owned by 16 tx lanes
    __syncthreads();
    #pragma unroll
    for (int r = 0; r < 8; r++) {
        int t = ty * 8 + r;
        rV[t * 17 + tx] = bestV[r];
        rI[t * 17 + tx] = __int_as_float(bestI[r]);
    }
    __syncthreads();
    if (tid < TM) {
        int t = tid;
        float bv = rV[t * 17];
        int   bi = __float_as_int(rI[t * 17]);
        #pragma unroll
        for (int x = 1; x < 16; x++) {
            float v = rV[t * 17 + x];
            int   i = __float_as_int(rI[t * 17 + x]);
            if (v < bv || (v == bv && i < bi)) { bv = v; bi = i; }
        }
        int n = n0 + t;
        g_idx[n] = bi;
        dout[IDX_OFF + n] = (float)bi;
    }
}

// ---------------------------------------------------------------------------
// Kernel 3: gather z_q via smem transpose tile -> both sides coalesced.
// Block handles 32 tokens x 256 channels.
// ---------------------------------------------------------------------------
#define GTOK 32
__global__ void __launch_bounds__(256) gather_kernel(const float* __restrict__ z,
                                                     const float* __restrict__ cb,
                                                     float* __restrict__ dout) {
    __shared__ float zq[GTOK][257];
    __shared__ int   idxs[GTOK];
    __shared__ float ws[8];

    const int tid = threadIdx.x;
    const int n0  = blockIdx.x * GTOK;
    const int b   = n0 / HW;
    const int hw0 = n0 % HW;

    if (tid < GTOK) idxs[tid] = g_idx[n0 + tid];
    __syncthreads();

    // load 32 codebook rows, coalesced over c
    #pragma unroll 4
    for (int t = 0; t < GTOK; t++) {
        zq[t][tid] = cb[(size_t)idxs[t] * D + tid];
    }
    __syncthreads();

    // write straight-through output, coalesced over t (32 consecutive hw)
    const int t  = tid & 31;
    const int c0 = tid >> 5;           // 0..7, each warp owns 32 channels
    float s = 0.f;
    const float* zb = z    + (size_t)b * CC * HW + hw0 + t;
    float*       ob = dout + (size_t)b * CC * HW + hw0 + t;
    #pragma unroll 8
    for (int it = 0; it < 32; it++) {
        int c = c0 * 32 + it;
        float zv = zb[(size_t)c * HW];
        float d  = zq[t][c] - zv;
        ob[(size_t)c * HW] = zv + d;   // z + sg(z_q - z), exact fp32 expr
        s = fmaf(d, d, s);
    }

    #pragma unroll
    for (int o = 16; o; o >>= 1) s += __shfl_xor_sync(0xffffffffu, s, o);
    if ((tid & 31) == 0) ws[tid >> 5] = s;
    __syncthreads();
    if (tid < 8) {
        float v = ws[tid];
        #pragma unroll
        for (int o = 4; o; o >>= 1) v += __shfl_xor_sync(0xffu, v, o);
        if (tid == 0) g_partial[blockIdx.x] = v;
    }
}

// ---------------------------------------------------------------------------
// Kernel 4: fixed-order final reduction -> deterministic scalars
// ---------------------------------------------------------------------------
__global__ void __launch_bounds__(256) finalize_kernel(float* __restrict__ dout) {
    __shared__ float sh[256];
    float s = 0.f;
    for (int i = threadIdx.x; i < GRID_C; i += 256) s += g_partial[i];
    sh[threadIdx.x] = s;
    __syncthreads();
    for (int o = 128; o; o >>= 1) {
        if (threadIdx.x < o) sh[threadIdx.x] += sh[threadIdx.x + o];
        __syncthreads();
    }
    if (threadIdx.x == 0) {
        dout[LOSS_OFF] = sh[0] * (2.0f / (float)ZQ_ELEMS);
        dout[CLS_OFF]  = 0.0f;
    }
}

// ---------------------------------------------------------------------------
extern "C" void kernel_launch(void* const* d_in, const int* in_sizes, int n_in,
                              void* d_out, int out_size) {
    const float* z  = (const float*)d_in[0];   // [B,C,H,W] fp32
    const float* cb = (const float*)d_in[1];   // [NE, D]   fp32
    float* out = (float*)d_out;

    cudaFuncSetAttribute(argmin_kernel,
                         cudaFuncAttributeMaxDynamicSharedMemorySize,
                         ARGMIN_SMEM_BYTES);

    cnorm_kernel <<<NE / 8, 256>>>(cb);
    argmin_kernel<<<NTOK / TM, 256, ARGMIN_SMEM_BYTES>>>(z, cb, out);
    gather_kernel<<<NTOK / GTOK, 256>>>(z, cb, out);
    finalize_kernel<<<1, 256>>>(out);
}

// round 4
// speedup vs baseline: 1.5379x; 1.1663x over previous
#include <cuda_runtime.h>

// Problem constants
#define B_    16
#define CC    256
#define HW    4096            // H*W
#define NTOK  65536           // B*H*W
#define NE    1024            // codebook entries
#define D     256             // e_dim
#define ZQ_ELEMS (NTOK * CC)  // 16777216
#define LOSS_OFF ZQ_ELEMS
#define CLS_OFF  (ZQ_ELEMS + 1)
#define IDX_OFF  (ZQ_ELEMS + 2)

// Tiling for the fused GEMM+argmin
#define TM 128        // tokens per block
#define TN 128        // codes per j-tile
#define KB 32         // k-chunk
#define NCHUNK 64     // (NE/TN) * (D/KB) = 8 * 8
#define BPITCH 129    // ull pitch of Bs rows (odd -> conflict-free)
#define BUFU (KB * BPITCH)
#define GRID_C 2048

typedef unsigned long long ull;

// Scratch (no allocations allowed)
__device__ int   g_idx[NTOK];
__device__ float g_cnorm[NE];
__device__ float g_partial[GRID_C];

// ---------------------------------------------------------------------------
// packed fp32x2 helpers (Blackwell full-rate fp32 path)
// ---------------------------------------------------------------------------
__device__ __forceinline__ ull pack2(float x) {
    ull r; asm("mov.b64 %0, {%1, %1};" : "=l"(r) : "f"(x)); return r;
}
__device__ __forceinline__ void fma2(ull& d, ull a, ull b) {
    asm("fma.rn.f32x2 %0, %1, %2, %0;" : "+l"(d) : "l"(a), "l"(b));
}
__device__ __forceinline__ void unpack2(ull v, float& lo, float& hi) {
    asm("mov.b64 {%0, %1}, %2;" : "=f"(lo), "=f"(hi) : "l"(v));
}

// ---------------------------------------------------------------------------
// Kernel 1: per-code squared norms (warp per row)
// ---------------------------------------------------------------------------
__global__ void __launch_bounds__(256) cnorm_kernel(const float* __restrict__ cb) {
    int row  = blockIdx.x * 8 + (threadIdx.x >> 5);
    int lane = threadIdx.x & 31;
    const float* p = cb + (size_t)row * D;
    float s = 0.f;
    for (int k = lane; k < D; k += 32) { float v = p[k]; s = fmaf(v, v, s); }
    #pragma unroll
    for (int o = 16; o; o >>= 1) s += __shfl_xor_sync(0xffffffffu, s, o);
    if (lane == 0) g_cnorm[row] = s;
}

// ---------------------------------------------------------------------------
// Kernel 2: fused distance GEMM + argmin, packed f32x2 math.
// 256 threads: tx = tid&31 (code lane), ty = tid>>5 (token group, 0..7).
// A warp = one ty -> A loads are warp-uniform (pure smem broadcast).
// Per thread: 16 tokens (8 ull via 4 LDS.128) x 4 codes (4 LDS.64, dup) per kk,
// 32 FFMA2 -> FMA:LDS ratio 4:1, FMA-pipe bound.
// Smem: As 131072 + Bs2 2*32*129*8=66048 + cnS 4096 = 201216 B
// ---------------------------------------------------------------------------
#define ARGMIN_SMEM_BYTES (D*TM*4 + 2*BUFU*8 + NE*4)

__device__ __forceinline__ void ldg_chunk(const float* __restrict__ cb, int g,
                                          int tid, float4* st) {
    int j0 = (g >> 3) * TN;
    int k0 = (g & 7) * KB;
    #pragma unroll
    for (int l = 0; l < 4; l++) {
        int fid = tid + l * 256;       // 1024 float4 = TN*KB floats
        int j   = fid >> 3;            // 8 float4 per code row (32 floats)
        int kk  = (fid & 7) * 4;
        st[l] = *(const float4*)(cb + (size_t)(j0 + j) * D + k0 + kk);
    }
}
__device__ __forceinline__ void sts_chunk(ull* buf, int tid, const float4* st) {
    #pragma unroll
    for (int l = 0; l < 4; l++) {
        int fid = tid + l * 256;
        int j   = fid >> 3;
        int kk  = (fid & 7) * 4;
        buf[(kk + 0) * BPITCH + j] = pack2(st[l].x);
        buf[(kk + 1) * BPITCH + j] = pack2(st[l].y);
        buf[(kk + 2) * BPITCH + j] = pack2(st[l].z);
        buf[(kk + 3) * BPITCH + j] = pack2(st[l].w);
    }
}

__global__ void __launch_bounds__(256) argmin_kernel(const float* __restrict__ z,
                                                     const float* __restrict__ cb,
                                                     float* __restrict__ dout) {
    extern __shared__ float smem[];
    float* As  = smem;                                   // [D][TM]
    ull*   Bs2 = (ull*)(smem + D * TM);                  // [2][KB][BPITCH]
    float* cnS = (float*)(Bs2 + 2 * BUFU);               // [NE]

    const int tid = threadIdx.x;
    const int tx  = tid & 31;     // code lane
    const int ty  = tid >> 5;     // token group (warp id)

    const int n0  = blockIdx.x * TM;     // 4096 % 128 == 0 -> never crosses b
    const int b   = n0 / HW;
    const int rem = n0 % HW;
    const float* zbase = z + (size_t)b * CC * HW + rem;

    // Load z tile: As[k][t] = z[b, k, rem+t]   (coalesced across t)
    for (int i = tid; i < D * TM; i += 256) {
        int k = i >> 7;
        int t = i & (TM - 1);
        As[k * TM + t] = zbase[(size_t)k * HW + t];
    }
    for (int i = tid; i < NE; i += 256) cnS[i] = g_cnorm[i];

    // prefetch chunk 0
    {
        float4 st[4];
        ldg_chunk(cb, 0, tid, st);
        sts_chunk(Bs2, tid, st);
    }
    __syncthreads();

    float bestV[16];
    int   bestI[16];
    #pragma unroll
    for (int r = 0; r < 16; r++) { bestV[r] = 3.4e38f; bestI[r] = 0; }

    ull acc[8][4];
    const ull* Ap = (const ull*)As;

    for (int g = 0; g < NCHUNK; g++) {
        const int ck = g & 7;
        if (ck == 0) {
            #pragma unroll
            for (int p = 0; p < 8; p++)
                #pragma unroll
                for (int c = 0; c < 4; c++) acc[p][c] = 0ull;
        }
        float4 st[4];
        if (g < NCHUNK - 1) ldg_chunk(cb, g + 1, tid, st);

        const ull* Bb = Bs2 + (g & 1) * BUFU;
        const int  k0 = ck * KB;
        #pragma unroll 4
        for (int kk = 0; kk < KB; kk++) {
            // A: warp-uniform broadcast, 4x LDS.128 -> 8 token-pair ulls
            const ulonglong2* ar =
                (const ulonglong2*)(Ap + (k0 + kk) * (TM / 2)) + ty * 4;
            ulonglong2 A0 = ar[0], A1 = ar[1], A2 = ar[2], A3 = ar[3];
            ull a0 = A0.x, a1 = A0.y, a2 = A1.x, a3 = A1.y;
            ull a4 = A2.x, a5 = A2.y, a6 = A3.x, a7 = A3.y;
            // B: 4x LDS.64 (dup-packed)
            const ull* br = Bb + kk * BPITCH + tx;
            ull b0 = br[0], b1 = br[32], b2 = br[64], b3 = br[96];

            fma2(acc[0][0], a0, b0); fma2(acc[1][0], a1, b0);
            fma2(acc[2][0], a2, b0); fma2(acc[3][0], a3, b0);
            fma2(acc[4][0], a4, b0); fma2(acc[5][0], a5, b0);
            fma2(acc[6][0], a6, b0); fma2(acc[7][0], a7, b0);
            fma2(acc[0][1], a0, b1); fma2(acc[1][1], a1, b1);
            fma2(acc[2][1], a2, b1); fma2(acc[3][1], a3, b1);
            fma2(acc[4][1], a4, b1); fma2(acc[5][1], a5, b1);
            fma2(acc[6][1], a6, b1); fma2(acc[7][1], a7, b1);
            fma2(acc[0][2], a0, b2); fma2(acc[1][2], a1, b2);
            fma2(acc[2][2], a2, b2); fma2(acc[3][2], a3, b2);
            fma2(acc[4][2], a4, b2); fma2(acc[5][2], a5, b2);
            fma2(acc[6][2], a6, b2); fma2(acc[7][2], a7, b2);
            fma2(acc[0][3], a0, b3); fma2(acc[1][3], a1, b3);
            fma2(acc[2][3], a2, b3); fma2(acc[3][3], a3, b3);
            fma2(acc[4][3], a4, b3); fma2(acc[5][3], a5, b3);
            fma2(acc[6][3], a6, b3); fma2(acc[7][3], a7, b3);
        }
        if (g < NCHUNK - 1) sts_chunk(Bs2 + ((g + 1) & 1) * BUFU, tid, st);
        __syncthreads();

        if (ck == 7) {
            const int j0 = (g >> 3) * TN;
            #pragma unroll
            for (int c = 0; c < 4; c++) {
                int j = j0 + tx + 32 * c;
                float cn = cnS[j];
                #pragma unroll
                for (int p = 0; p < 8; p++) {
                    float lo, hi;
                    unpack2(acc[p][c], lo, hi);
                    float v0 = fmaf(-2.f, lo, cn);
                    float v1 = fmaf(-2.f, hi, cn);
                    // j strictly ascending per token -> strict < keeps lowest idx
                    if (v0 < bestV[2 * p])     { bestV[2 * p]     = v0; bestI[2 * p]     = j; }
                    if (v1 < bestV[2 * p + 1]) { bestV[2 * p + 1] = v1; bestI[2 * p + 1] = j; }
                }
            }
        }
    }

    // Warp-shuffle argmin: warp = one ty, lanes hold the 32 candidates/token
    #pragma unroll
    for (int r = 0; r < 16; r++) {
        float bv = bestV[r];
        int   bi = bestI[r];
        #pragma unroll
        for (int o = 16; o; o >>= 1) {
            float ov = __shfl_xor_sync(0xffffffffu, bv, o);
            int   oi = __shfl_xor_sync(0xffffffffu, bi, o);
            if (ov < bv || (ov == bv && oi < bi)) { bv = ov; bi = oi; }
        }
        if (tx == 0) {
            int n = n0 + ty * 16 + r;
            g_idx[n] = bi;
            dout[IDX_OFF + n] = (float)bi;
        }
    }
}

// ---------------------------------------------------------------------------
// Kernel 3: gather z_q via smem transpose tile -> both sides coalesced.
// Block handles 32 tokens x 256 channels.
// ---------------------------------------------------------------------------
#define GTOK 32
__global__ void __launch_bounds__(256) gather_kernel(const float* __restrict__ z,
                                                     const float* __restrict__ cb,
                                                     float* __restrict__ dout) {
    __shared__ float zq[GTOK][257];
    __shared__ int   idxs[GTOK];
    __shared__ float ws[8];

    const int tid = threadIdx.x;
    const int n0  = blockIdx.x * GTOK;
    const int b   = n0 / HW;
    const int hw0 = n0 % HW;

    if (tid < GTOK) idxs[tid] = g_idx[n0 + tid];
    __syncthreads();

    #pragma unroll 4
    for (int t = 0; t < GTOK; t++) {
        zq[t][tid] = cb[(size_t)idxs[t] * D + tid];
    }
    __syncthreads();

    const int t  = tid & 31;
    const int c0 = tid >> 5;
    float s = 0.f;
    const float* zb = z    + (size_t)b * CC * HW + hw0 + t;
    float*       ob = dout + (size_t)b * CC * HW + hw0 + t;
    #pragma unroll 8
    for (int it = 0; it < 32; it++) {
        int c = c0 * 32 + it;
        float zv = zb[(size_t)c * HW];
        float d  = zq[t][c] - zv;
        ob[(size_t)c * HW] = zv + d;   // z + sg(z_q - z), exact fp32 expr
        s = fmaf(d, d, s);
    }

    #pragma unroll
    for (int o = 16; o; o >>= 1) s += __shfl_xor_sync(0xffffffffu, s, o);
    if ((tid & 31) == 0) ws[tid >> 5] = s;
    __syncthreads();
    if (tid < 8) {
        float v = ws[tid];
        #pragma unroll
        for (int o = 4; o; o >>= 1) v += __shfl_xor_sync(0xffu, v, o);
        if (tid == 0) g_partial[blockIdx.x] = v;
    }
}

// ---------------------------------------------------------------------------
// Kernel 4: fixed-order final reduction -> deterministic scalars
// ---------------------------------------------------------------------------
__global__ void __launch_bounds__(256) finalize_kernel(float* __restrict__ dout) {
    __shared__ float sh[256];
    float s = 0.f;
    for (int i = threadIdx.x; i < GRID_C; i += 256) s += g_partial[i];
    sh[threadIdx.x] = s;
    __syncthreads();
    for (int o = 128; o; o >>= 1) {
        if (threadIdx.x < o) sh[threadIdx.x] += sh[threadIdx.x + o];
        __syncthreads();
    }
    if (threadIdx.x == 0) {
        dout[LOSS_OFF] = sh[0] * (2.0f / (float)ZQ_ELEMS);
        dout[CLS_OFF]  = 0.0f;
    }
}

// ---------------------------------------------------------------------------
extern "C" void kernel_launch(void* const* d_in, const int* in_sizes, int n_in,
                              void* d_out, int out_size) {
    const float* z  = (const float*)d_in[0];   // [B,C,H,W] fp32
    const float* cb = (const float*)d_in[1];   // [NE, D]   fp32
    float* out = (float*)d_out;

    cudaFuncSetAttribute(argmin_kernel,
                         cudaFuncAttributeMaxDynamicSharedMemorySize,
                         ARGMIN_SMEM_BYTES);

    cnorm_kernel <<<NE / 8, 256>>>(cb);
    argmin_kernel<<<NTOK / TM, 256, ARGMIN_SMEM_BYTES>>>(z, cb, out);
    gather_kernel<<<NTOK / GTOK, 256>>>(z, cb, out);
    finalize_kernel<<<1, 256>>>(out);
}

// round 5
// speedup vs baseline: 2.1033x; 1.3676x over previous
#include <cuda_runtime.h>

// Problem constants
#define B_    16
#define CC    256
#define HW    4096            // H*W
#define NTOK  65536           // B*H*W
#define NE    1024            // codebook entries
#define D     256             // e_dim
#define ZQ_ELEMS (NTOK * CC)  // 16777216
#define LOSS_OFF ZQ_ELEMS
#define CLS_OFF  (ZQ_ELEMS + 1)
#define IDX_OFF  (ZQ_ELEMS + 2)

// Tiling for the fused GEMM+argmin
#define TM 64         // tokens per block
#define TN 256        // codes per j-tile
#define KB 8          // k-chunk
#define NCHUNK 128    // (NE/TN=4) * (D/KB=32)
#define BPU 130       // ull pitch of Bs rows (even -> LDS.128-alignable)
#define BPF 260       // float pitch (= 2*BPU)
#define GRID_C 2048

typedef unsigned long long ull;

// Scratch (no allocations allowed)
__device__ int   g_idx[NTOK];
__device__ float g_cnorm[NE];
__device__ float g_partial[GRID_C];

// ---------------------------------------------------------------------------
// packed fp32x2 helpers (Blackwell full-rate fp32 path)
// ---------------------------------------------------------------------------
__device__ __forceinline__ ull pack2(float x) {
    ull r; asm("mov.b64 %0, {%1, %1};" : "=l"(r) : "f"(x)); return r;
}
__device__ __forceinline__ void fma2(ull& d, ull a, ull b) {
    asm("fma.rn.f32x2 %0, %1, %2, %0;" : "+l"(d) : "l"(a), "l"(b));
}
__device__ __forceinline__ void unpack2(ull v, float& lo, float& hi) {
    asm("mov.b64 {%0, %1}, %2;" : "=f"(lo), "=f"(hi) : "l"(v));
}

// ---------------------------------------------------------------------------
// Kernel 1: per-code squared norms (warp per row)
// ---------------------------------------------------------------------------
__global__ void __launch_bounds__(256) cnorm_kernel(const float* __restrict__ cb) {
    int row  = blockIdx.x * 8 + (threadIdx.x >> 5);
    int lane = threadIdx.x & 31;
    const float* p = cb + (size_t)row * D;
    float s = 0.f;
    for (int k = lane; k < D; k += 32) { float v = p[k]; s = fmaf(v, v, s); }
    #pragma unroll
    for (int o = 16; o; o >>= 1) s += __shfl_xor_sync(0xffffffffu, s, o);
    if (lane == 0) g_cnorm[row] = s;
}

// ---------------------------------------------------------------------------
// Kernel 2: fused distance GEMM + argmin, packed f32x2, 2 CTAs/SM.
// 256 threads = 8 warps; warp w owns tokens n0 + w*8 .. +7 (A loads are
// warp-uniform smem broadcasts, duplicated into f32x2 pairs in registers).
// B stored as CODE-PAIR packed ulls (no duplication -> half crossbar bytes):
//   Bs[kk][jp] = (cb[j0+2jp][k], cb[j0+2jp+1][k])
// Per thread per kk: 2 LDS.128 (A, uniform) + 2 LDS.128 (B) + 32 FFMA2.
// Smem: As 64KB (float [256][64]) + Bs2 2*8*130*8=16640 + cn 4096 = 86272 B
//   -> 2 CTAs/SM, 4 warps/SMSP, barriers/latency overlap across CTAs.
// ---------------------------------------------------------------------------
#define ARGMIN_SMEM_BYTES (D*TM*4 + 2*KB*BPU*8 + NE*4)

__device__ __forceinline__ void ldg_chunk(const float* __restrict__ cb, int g,
                                          int tid, float4* st) {
    int j0 = (g >> 5) * TN;
    int k0 = (g & 31) * KB;
    #pragma unroll
    for (int l = 0; l < 2; l++) {
        int fid = tid + l * 256;        // 512 float4 = TN*KB floats
        int j   = fid >> 1;             // 2 float4 per code row (8 floats)
        int kk4 = (fid & 1) * 4;
        st[l] = *(const float4*)(cb + (size_t)(j0 + j) * D + k0 + kk4);
    }
}
__device__ __forceinline__ void sts_chunk(ull* buf, int tid, const float4* st) {
    float* bf = (float*)buf;            // float view: [kk][j] pitch BPF
    #pragma unroll
    for (int l = 0; l < 2; l++) {
        int fid = tid + l * 256;
        int j   = fid >> 1;
        int kk4 = (fid & 1) * 4;
        bf[(kk4 + 0) * BPF + j] = st[l].x;
        bf[(kk4 + 1) * BPF + j] = st[l].y;
        bf[(kk4 + 2) * BPF + j] = st[l].z;
        bf[(kk4 + 3) * BPF + j] = st[l].w;
    }
}

__global__ void __launch_bounds__(256, 2) argmin_kernel(const float* __restrict__ z,
                                                        const float* __restrict__ cb,
                                                        float* __restrict__ dout) {
    extern __shared__ float smem[];
    float* As  = smem;                                 // [D][TM] floats
    ull*   Bs2 = (ull*)(smem + D * TM);                // [2][KB][BPU]
    float* cnS = (float*)(Bs2 + 2 * KB * BPU);         // [NE]

    const int tid = threadIdx.x;
    const int tx  = tid & 31;     // code lane
    const int w   = tid >> 5;     // warp id = token group

    const int n0  = blockIdx.x * TM;     // 4096 % 64 == 0 -> never crosses b
    const int b   = n0 >> 12;
    const int rem = n0 & (HW - 1);
    const float* zbase = z + (size_t)b * CC * HW + rem;

    // Load z tile: As[k][t] = z[b, k, rem+t]  (float4, coalesced)
    for (int i = tid; i < D * TM / 4; i += 256) {
        int k  = i >> 4;
        int t4 = (i & 15) * 4;
        *(float4*)(As + k * TM + t4) =
            *(const float4*)(zbase + (size_t)k * HW + t4);
    }
    for (int i = tid; i < NE; i += 256) cnS[i] = g_cnorm[i];

    // prefetch chunk 0
    float4 st[2];
    ldg_chunk(cb, 0, tid, st);
    sts_chunk(Bs2, tid, st);
    __syncthreads();

    float bestV[8];
    int   bestI[8];
    #pragma unroll
    for (int r = 0; r < 8; r++) { bestV[r] = 3.4e38f; bestI[r] = 0; }

    ull acc[8][4];

    for (int g = 0; g < NCHUNK; g++) {
        const int ck = g & 31;
        if (ck == 0) {
            #pragma unroll
            for (int p = 0; p < 8; p++)
                #pragma unroll
                for (int c = 0; c < 4; c++) acc[p][c] = 0ull;
        }
        if (g < NCHUNK - 1) ldg_chunk(cb, g + 1, tid, st);

        const ull* Bb = Bs2 + (g & 1) * KB * BPU;
        const int  k0 = ck * KB;
        #pragma unroll
        for (int kk = 0; kk < KB; kk++) {
            const int k = k0 + kk;
            // A: warp-uniform broadcast, dup into f32x2 in registers
            float4 A0 = *(const float4*)(As + k * TM + w * 8);
            float4 A1 = *(const float4*)(As + k * TM + w * 8 + 4);
            ull a0 = pack2(A0.x), a1 = pack2(A0.y), a2 = pack2(A0.z), a3 = pack2(A0.w);
            ull a4 = pack2(A1.x), a5 = pack2(A1.y), a6 = pack2(A1.z), a7 = pack2(A1.w);
            // B: code-pair packed, 2x LDS.128
            ulonglong2 B01 = *(const ulonglong2*)(Bb + kk * BPU + 2 * tx);
            ulonglong2 B23 = *(const ulonglong2*)(Bb + kk * BPU + 64 + 2 * tx);
            ull b0 = B01.x, b1 = B01.y, b2 = B23.x, b3 = B23.y;

            fma2(acc[0][0], a0, b0); fma2(acc[1][0], a1, b0);
            fma2(acc[2][0], a2, b0); fma2(acc[3][0], a3, b0);
            fma2(acc[4][0], a4, b0); fma2(acc[5][0], a5, b0);
            fma2(acc[6][0], a6, b0); fma2(acc[7][0], a7, b0);
            fma2(acc[0][1], a0, b1); fma2(acc[1][1], a1, b1);
            fma2(acc[2][1], a2, b1); fma2(acc[3][1], a3, b1);
            fma2(acc[4][1], a4, b1); fma2(acc[5][1], a5, b1);
            fma2(acc[6][1], a6, b1); fma2(acc[7][1], a7, b1);
            fma2(acc[0][2], a0, b2); fma2(acc[1][2], a1, b2);
            fma2(acc[2][2], a2, b2); fma2(acc[3][2], a3, b2);
            fma2(acc[4][2], a4, b2); fma2(acc[5][2], a5, b2);
            fma2(acc[6][2], a6, b2); fma2(acc[7][2], a7, b2);
            fma2(acc[0][3], a0, b3); fma2(acc[1][3], a1, b3);
            fma2(acc[2][3], a2, b3); fma2(acc[3][3], a3, b3);
            fma2(acc[4][3], a4, b3); fma2(acc[5][3], a5, b3);
            fma2(acc[6][3], a6, b3); fma2(acc[7][3], a7, b3);
        }
        if (g < NCHUNK - 1) sts_chunk(Bs2 + ((g + 1) & 1) * KB * BPU, tid, st);
        __syncthreads();

        if (ck == 31) {
            const int j0 = (g >> 5) * TN;
            const int jb = j0 + 4 * tx;
            // candidate codes per thread, ascending:
            //   jb, jb+1, jb+2, jb+3, jb+128 .. jb+131
            float4 cnL = *(const float4*)(cnS + jb);
            float4 cnH = *(const float4*)(cnS + jb + 128);
            #pragma unroll
            for (int p = 0; p < 8; p++) {
                float l0, h0, l1, h1, l2, h2, l3, h3;
                unpack2(acc[p][0], l0, h0);   // codes jb, jb+1
                unpack2(acc[p][1], l1, h1);   // codes jb+2, jb+3
                unpack2(acc[p][2], l2, h2);   // codes jb+128, jb+129
                unpack2(acc[p][3], l3, h3);   // codes jb+130, jb+131
                float v; 
                v = fmaf(-2.f, l0, cnL.x); if (v < bestV[p]) { bestV[p] = v; bestI[p] = jb;       }
                v = fmaf(-2.f, h0, cnL.y); if (v < bestV[p]) { bestV[p] = v; bestI[p] = jb + 1;   }
                v = fmaf(-2.f, l1, cnL.z); if (v < bestV[p]) { bestV[p] = v; bestI[p] = jb + 2;   }
                v = fmaf(-2.f, h1, cnL.w); if (v < bestV[p]) { bestV[p] = v; bestI[p] = jb + 3;   }
                v = fmaf(-2.f, l2, cnH.x); if (v < bestV[p]) { bestV[p] = v; bestI[p] = jb + 128; }
                v = fmaf(-2.f, h2, cnH.y); if (v < bestV[p]) { bestV[p] = v; bestI[p] = jb + 129; }
                v = fmaf(-2.f, l3, cnH.z); if (v < bestV[p]) { bestV[p] = v; bestI[p] = jb + 130; }
                v = fmaf(-2.f, h3, cnH.w); if (v < bestV[p]) { bestV[p] = v; bestI[p] = jb + 131; }
            }
        }
    }

    // Warp-shuffle argmin: warp w holds all 32 lanes' candidates for its tokens
    #pragma unroll
    for (int p = 0; p < 8; p++) {
        float bv = bestV[p];
        int   bi = bestI[p];
        #pragma unroll
        for (int o = 16; o; o >>= 1) {
            float ov = __shfl_xor_sync(0xffffffffu, bv, o);
            int   oi = __shfl_xor_sync(0xffffffffu, bi, o);
            if (ov < bv || (ov == bv && oi < bi)) { bv = ov; bi = oi; }
        }
        if (tx == 0) {
            int n = n0 + w * 8 + p;
            g_idx[n] = bi;
            dout[IDX_OFF + n] = (float)bi;
        }
    }
}

// ---------------------------------------------------------------------------
// Kernel 3: gather z_q via smem transpose tile -> both sides coalesced.
// Block handles 32 tokens x 256 channels.
// ---------------------------------------------------------------------------
#define GTOK 32
__global__ void __launch_bounds__(256) gather_kernel(const float* __restrict__ z,
                                                     const float* __restrict__ cb,
                                                     float* __restrict__ dout) {
    __shared__ float zq[GTOK][257];
    __shared__ int   idxs[GTOK];
    __shared__ float ws[8];

    const int tid = threadIdx.x;
    const int n0  = blockIdx.x * GTOK;
    const int b   = n0 / HW;
    const int hw0 = n0 % HW;

    if (tid < GTOK) idxs[tid] = g_idx[n0 + tid];
    __syncthreads();

    #pragma unroll 4
    for (int t = 0; t < GTOK; t++) {
        zq[t][tid] = cb[(size_t)idxs[t] * D + tid];
    }
    __syncthreads();

    const int t  = tid & 31;
    const int c0 = tid >> 5;
    float s = 0.f;
    const float* zb = z    + (size_t)b * CC * HW + hw0 + t;
    float*       ob = dout + (size_t)b * CC * HW + hw0 + t;
    #pragma unroll 8
    for (int it = 0; it < 32; it++) {
        int c = c0 * 32 + it;
        float zv = zb[(size_t)c * HW];
        float d  = zq[t][c] - zv;
        ob[(size_t)c * HW] = zv + d;   // z + sg(z_q - z), exact fp32 expr
        s = fmaf(d, d, s);
    }

    #pragma unroll
    for (int o = 16; o; o >>= 1) s += __shfl_xor_sync(0xffffffffu, s, o);
    if ((tid & 31) == 0) ws[tid >> 5] = s;
    __syncthreads();
    if (tid < 8) {
        float v = ws[tid];
        #pragma unroll
        for (int o = 4; o; o >>= 1) v += __shfl_xor_sync(0xffu, v, o);
        if (tid == 0) g_partial[blockIdx.x] = v;
    }
}

// ---------------------------------------------------------------------------
// Kernel 4: fixed-order final reduction -> deterministic scalars
// ---------------------------------------------------------------------------
__global__ void __launch_bounds__(256) finalize_kernel(float* __restrict__ dout) {
    __shared__ float sh[256];
    float s = 0.f;
    for (int i = threadIdx.x; i < GRID_C; i += 256) s += g_partial[i];
    sh[threadIdx.x] = s;
    __syncthreads();
    for (int o = 128; o; o >>= 1) {
        if (threadIdx.x < o) sh[threadIdx.x] += sh[threadIdx.x + o];
        __syncthreads();
    }
    if (threadIdx.x == 0) {
        dout[LOSS_OFF] = sh[0] * (2.0f / (float)ZQ_ELEMS);
        dout[CLS_OFF]  = 0.0f;
    }
}

// ---------------------------------------------------------------------------
extern "C" void kernel_launch(void* const* d_in, const int* in_sizes, int n_in,
                              void* d_out, int out_size) {
    const float* z  = (const float*)d_in[0];   // [B,C,H,W] fp32
    const float* cb = (const float*)d_in[1];   // [NE, D]   fp32
    float* out = (float*)d_out;

    cudaFuncSetAttribute(argmin_kernel,
                         cudaFuncAttributeMaxDynamicSharedMemorySize,
                         ARGMIN_SMEM_BYTES);

    cnorm_kernel <<<NE / 8, 256>>>(cb);
    argmin_kernel<<<NTOK / TM, 256, ARGMIN_SMEM_BYTES>>>(z, cb, out);
    gather_kernel<<<NTOK / GTOK, 256>>>(z, cb, out);
    finalize_kernel<<<1, 256>>>(out);
}

// round 8
// speedup vs baseline: 3.5660x; 1.6954x over previous
#include <cuda_runtime.h>
#include <cuda_fp16.h>
#include <cstdint>

// Problem constants
#define B_    16
#define CC    256
#define HW    4096
#define NTOK  65536
#define NE    1024
#define D     256
#define ZQ_ELEMS (NTOK * CC)
#define LOSS_OFF ZQ_ELEMS
#define CLS_OFF  (ZQ_ELEMS + 1)
#define IDX_OFF  (ZQ_ELEMS + 2)
#define GRID_C 2048

#define MARGIN 1.0f          // > 2x worst-case fp16 screening error (0.43)

// Pass-1 tiling: CTA = 128 tokens x NE codes, j-tiles of 64, k-chunks of 64
#define TM   128
#define JT   64
#define KC   64
#define NCHUNK 64            // 16 j-tiles * 4 k-chunks

// Pass-1 smem layout (bytes)
#define AS_PITCH_H 264       // halves per token row (256 + 8 pad)
#define AS_PITCH_U 132
#define OFF_AS 0             // half As[128][264] = 67584
#define BS_PITCH_U 36        // uint (half2) per code row (32 + 4 pad)
#define BS_SZ  9216          // 64 * 36 * 4
#define OFF_BS 67584         // two stages
#define OFF_CN (67584 + 2 * BS_SZ)     // 86016
#define P1_SMEM (OFF_CN + 4096)        // 90112

// Scratch (static device memory is the sanctioned workaround)
__device__ float g_dist[(size_t)NTOK * NE];   // 256 MB approx distances
__device__ int   g_idx[NTOK];
__device__ float g_cnorm[NE];
__device__ float g_partial[GRID_C];

// ---------------------------------------------------------------------------
// helpers
// ---------------------------------------------------------------------------
__device__ __forceinline__ uint32_t pack_h2(float x, float y) {
    __half2 h = __floats2half2_rn(x, y);
    return *reinterpret_cast<uint32_t*>(&h);
}
__device__ __forceinline__ void mma_h16(float& d0, float& d1, float& d2, float& d3,
                                        uint32_t a0, uint32_t a1, uint32_t a2, uint32_t a3,
                                        uint32_t b0, uint32_t b1) {
    asm volatile(
        "mma.sync.aligned.m16n8k16.row.col.f32.f16.f16.f32 "
        "{%0,%1,%2,%3}, {%4,%5,%6,%7}, {%8,%9}, {%0,%1,%2,%3};\n"
        : "+f"(d0), "+f"(d1), "+f"(d2), "+f"(d3)
        : "r"(a0), "r"(a1), "r"(a2), "r"(a3), "r"(b0), "r"(b1));
}

// ---------------------------------------------------------------------------
// Kernel 1: per-code squared norms (warp per row)
// ---------------------------------------------------------------------------
__global__ void __launch_bounds__(256) cnorm_kernel(const float* __restrict__ cb) {
    int row  = blockIdx.x * 8 + (threadIdx.x >> 5);
    int lane = threadIdx.x & 31;
    const float* p = cb + (size_t)row * D;
    float s = 0.f;
    for (int k = lane; k < D; k += 32) { float v = p[k]; s = fmaf(v, v, s); }
    #pragma unroll
    for (int o = 16; o; o >>= 1) s += __shfl_xor_sync(0xffffffffu, s, o);
    if (lane == 0) g_cnorm[row] = s;
}

// ---------------------------------------------------------------------------
// Kernel 2 (pass 1): fp16 HMMA screening GEMM.
// dist_approx[n][j] = ||c_j||^2 + sum_k fp16(z)*fp16(-2 c).
// 256 threads = 8 warps; warp w owns tokens w*16 .. +15 (rows r, r+8).
// A resident in smem as half [128][264]; B staged per (j-tile, k-chunk)
// as half2-packed uints, double buffered. mma m16n8k16, acc fp32.
// ---------------------------------------------------------------------------
__global__ void __launch_bounds__(256, 2) dist_kernel(const float* __restrict__ z,
                                                      const float* __restrict__ cb) {
    extern __shared__ char smem[];
    __half*   As_h = (__half*)(smem + OFF_AS);
    uint32_t* As_u = (uint32_t*)(smem + OFF_AS);
    float*    cnS  = (float*)(smem + OFF_CN);

    const int tid  = threadIdx.x;
    const int w    = tid >> 5;
    const int lane = tid & 31;
    const int r    = lane >> 2;      // row-in-frag 0..7
    const int q    = lane & 3;       // quad column 0..3

    const int n0  = blockIdx.x * TM;
    const int b   = n0 >> 12;
    const int rem = n0 & (HW - 1);

    // Stage A: z[b, k, rem+t] -> half As[t][k]  (coalesced loads over t)
    for (int i = tid; i < D * TM / 4; i += 256) {
        int k  = i >> 5;
        int t4 = (i & 31) * 4;
        float4 v = *(const float4*)(z + (size_t)b * CC * HW + (size_t)k * HW + rem + t4);
        As_h[(t4 + 0) * AS_PITCH_H + k] = __float2half_rn(v.x);
        As_h[(t4 + 1) * AS_PITCH_H + k] = __float2half_rn(v.y);
        As_h[(t4 + 2) * AS_PITCH_H + k] = __float2half_rn(v.z);
        As_h[(t4 + 3) * AS_PITCH_H + k] = __float2half_rn(v.w);
    }
    for (int i = tid; i < NE; i += 256) cnS[i] = g_cnorm[i];

    // B staging task: thread -> (n = tid>>2, kq = tid&3), 16 floats
    const int bn  = tid >> 2;
    const int bkq = tid & 3;

    // prefetch chunk 0
    float4 pf[4];
    {
        const float* src = cb + (size_t)bn * D + bkq * 16;   // j0=0, kb0=0
        #pragma unroll
        for (int u = 0; u < 4; u++) pf[u] = *(const float4*)(src + u * 4);
        uint32_t* Bs = (uint32_t*)(smem + OFF_BS);
        #pragma unroll
        for (int u = 0; u < 4; u++) {
            Bs[bn * BS_PITCH_U + bkq * 8 + u * 2 + 0] = pack_h2(-2.f * pf[u].x, -2.f * pf[u].y);
            Bs[bn * BS_PITCH_U + bkq * 8 + u * 2 + 1] = pack_h2(-2.f * pf[u].z, -2.f * pf[u].w);
        }
    }
    __syncthreads();

    float acc[8][4];
    #pragma unroll
    for (int nt = 0; nt < 8; nt++)
        #pragma unroll
        for (int c = 0; c < 4; c++) acc[nt][c] = 0.f;

    const int t0      = w * 16;
    const int tokbase = n0 + t0;

    for (int g = 0; g < NCHUNK; g++) {
        const int jt = g >> 2;
        const int kc = g & 3;

        // prefetch next chunk's B from global
        if (g + 1 < NCHUNK) {
            const int j0n = ((g + 1) >> 2) * JT;
            const int kbn = ((g + 1) & 3) * KC;
            const float* src = cb + (size_t)(j0n + bn) * D + kbn + bkq * 16;
            #pragma unroll
            for (int u = 0; u < 4; u++) pf[u] = *(const float4*)(src + u * 4);
        }

        // compute chunk g from stage g&1
        const uint32_t* Bs = (const uint32_t*)(smem + OFF_BS + (g & 1) * BS_SZ);
        #pragma unroll
        for (int s = 0; s < 4; s++) {
            const int ah_base = (t0 + r) * AS_PITCH_U + kc * 32 + s * 8 + q;
            uint32_t a0 = As_u[ah_base];
            uint32_t a1 = As_u[ah_base + 8 * AS_PITCH_U];
            uint32_t a2 = As_u[ah_base + 4];
            uint32_t a3 = As_u[ah_base + 8 * AS_PITCH_U + 4];
            #pragma unroll
            for (int nt = 0; nt < 8; nt++) {
                const int jn = nt * 8 + (lane >> 2);
                uint32_t b0 = Bs[jn * BS_PITCH_U + s * 8 + q];
                uint32_t b1 = Bs[jn * BS_PITCH_U + s * 8 + q + 4];
                mma_h16(acc[nt][0], acc[nt][1], acc[nt][2], acc[nt][3],
                        a0, a1, a2, a3, b0, b1);
            }
        }

        // store next chunk into the other stage
        if (g + 1 < NCHUNK) {
            uint32_t* Bs2 = (uint32_t*)(smem + OFF_BS + ((g + 1) & 1) * BS_SZ);
            #pragma unroll
            for (int u = 0; u < 4; u++) {
                Bs2[bn * BS_PITCH_U + bkq * 8 + u * 2 + 0] = pack_h2(-2.f * pf[u].x, -2.f * pf[u].y);
                Bs2[bn * BS_PITCH_U + bkq * 8 + u * 2 + 1] = pack_h2(-2.f * pf[u].z, -2.f * pf[u].w);
            }
        }
        __syncthreads();

        // end of j-tile: add ||c||^2 and stream to g_dist, reset acc
        if (kc == 3) {
            #pragma unroll
            for (int nt = 0; nt < 8; nt++) {
                int j = jt * JT + nt * 8 + 2 * q;
                float c0 = cnS[j], c1 = cnS[j + 1];
                float2 v0 = make_float2(c0 + acc[nt][0], c1 + acc[nt][1]);
                float2 v1 = make_float2(c0 + acc[nt][2], c1 + acc[nt][3]);
                *(float2*)(g_dist + ((size_t)(tokbase + r) << 10) + j)     = v0;
                *(float2*)(g_dist + ((size_t)(tokbase + r + 8) << 10) + j) = v1;
                acc[nt][0] = acc[nt][1] = acc[nt][2] = acc[nt][3] = 0.f;
            }
        }
    }
}

// ---------------------------------------------------------------------------
// Kernel 3 (pass 2): exact argmin via margin rescoring.
// Block = 32 tokens; warp = 4 tokens. Per token: scan approx row, rescore
// all candidates within MARGIN of the approx min exactly in fp32.
// ---------------------------------------------------------------------------
__global__ void __launch_bounds__(256) argmin_kernel(const float* __restrict__ z,
                                                     const float* __restrict__ cb,
                                                     float* __restrict__ dout) {
    __shared__ float zs[32][260];
    const int tid  = threadIdx.x;
    const int w    = tid >> 5;
    const int lane = tid & 31;

    const int n0  = blockIdx.x * 32;
    const int b   = n0 >> 12;
    const int hw0 = n0 & (HW - 1);

    // stage z tile [t][k]
    for (int i = tid; i < D * 32 / 4; i += 256) {
        int k  = i >> 3;
        int t4 = (i & 7) * 4;
        float4 v = *(const float4*)(z + (size_t)b * CC * HW + (size_t)k * HW + hw0 + t4);
        zs[t4 + 0][k] = v.x; zs[t4 + 1][k] = v.y;
        zs[t4 + 2][k] = v.z; zs[t4 + 3][k] = v.w;
    }
    __syncthreads();

    for (int tt = 0; tt < 4; tt++) {
        const int t = w * 4 + tt;
        const int n = n0 + t;
        const float* drow = g_dist + ((size_t)n << 10);

        float dv[32];
        #pragma unroll
        for (int i = 0; i < 32; i++) dv[i] = drow[lane + 32 * i];

        float m = dv[0];
        #pragma unroll
        for (int i = 1; i < 32; i++) m = fminf(m, dv[i]);
        #pragma unroll
        for (int o = 16; o; o >>= 1) m = fminf(m, __shfl_xor_sync(0xffffffffu, m, o));
        const float thr = m + MARGIN;

        float best = 3.4e38f;
        int   bi   = 0;
        #pragma unroll
        for (int i = 0; i < 32; i++) {
            unsigned mask = __ballot_sync(0xffffffffu, dv[i] < thr);
            while (mask) {
                int bit = __ffs(mask) - 1;
                mask &= mask - 1;
                int j = i * 32 + bit;          // ascending j across i and bits
                const float* crow = cb + (size_t)j * D;
                float s = 0.f;
                #pragma unroll
                for (int u = 0; u < 8; u++)
                    s = fmaf(zs[t][lane + 32 * u], crow[lane + 32 * u], s);
                #pragma unroll
                for (int o = 16; o; o >>= 1) s += __shfl_xor_sync(0xffffffffu, s, o);
                float dist = g_cnorm[j] - 2.0f * s;
                if (dist < best) { best = dist; bi = j; }   // strict < keeps lowest j
            }
        }
        if (lane == 0) {
            g_idx[n] = bi;
            dout[IDX_OFF + n] = (float)bi;
        }
    }
}

// ---------------------------------------------------------------------------
// Kernel 4: gather z_q + straight-through output + partial loss
// ---------------------------------------------------------------------------
#define GTOK 32
__global__ void __launch_bounds__(256) gather_kernel(const float* __restrict__ z,
                                                     const float* __restrict__ cb,
                                                     float* __restrict__ dout) {
    __shared__ float zq[GTOK][257];
    __shared__ int   idxs[GTOK];
    __shared__ float ws[8];

    const int tid = threadIdx.x;
    const int n0  = blockIdx.x * GTOK;
    const int b   = n0 / HW;
    const int hw0 = n0 % HW;

    if (tid < GTOK) idxs[tid] = g_idx[n0 + tid];
    __syncthreads();

    #pragma unroll 4
    for (int t = 0; t < GTOK; t++) {
        zq[t][tid] = cb[(size_t)idxs[t] * D + tid];
    }
    __syncthreads();

    const int t  = tid & 31;
    const int c0 = tid >> 5;
    float s = 0.f;
    const float* zb = z    + (size_t)b * CC * HW + hw0 + t;
    float*       ob = dout + (size_t)b * CC * HW + hw0 + t;
    #pragma unroll 8
    for (int it = 0; it < 32; it++) {
        int c = c0 * 32 + it;
        float zv = zb[(size_t)c * HW];
        float d  = zq[t][c] - zv;
        ob[(size_t)c * HW] = zv + d;   // z + sg(z_q - z), exact fp32 expr
        s = fmaf(d, d, s);
    }

    #pragma unroll
    for (int o = 16; o; o >>= 1) s += __shfl_xor_sync(0xffffffffu, s, o);
    if ((tid & 31) == 0) ws[tid >> 5] = s;
    __syncthreads();
    if (tid < 8) {
        float v = ws[tid];
        #pragma unroll
        for (int o = 4; o; o >>= 1) v += __shfl_xor_sync(0xffu, v, o);
        if (tid == 0) g_partial[blockIdx.x] = v;
    }
}

// ---------------------------------------------------------------------------
// Kernel 5: deterministic final reduction
// ---------------------------------------------------------------------------
__global__ void __launch_bounds__(256) finalize_kernel(float* __restrict__ dout) {
    __shared__ float sh[256];
    float s = 0.f;
    for (int i = threadIdx.x; i < GRID_C; i += 256) s += g_partial[i];
    sh[threadIdx.x] = s;
    __syncthreads();
    for (int o = 128; o; o >>= 1) {
        if (threadIdx.x < o) sh[threadIdx.x] += sh[threadIdx.x + o];
        __syncthreads();
    }
    if (threadIdx.x == 0) {
        dout[LOSS_OFF] = sh[0] * (2.0f / (float)ZQ_ELEMS);
        dout[CLS_OFF]  = 0.0f;
    }
}

// ---------------------------------------------------------------------------
extern "C" void kernel_launch(void* const* d_in, const int* in_sizes, int n_in,
                              void* d_out, int out_size) {
    const float* z  = (const float*)d_in[0];   // [B,C,H,W] fp32
    const float* cb = (const float*)d_in[1];   // [NE, D]   fp32
    float* out = (float*)d_out;

    cudaFuncSetAttribute(dist_kernel,
                         cudaFuncAttributeMaxDynamicSharedMemorySize, P1_SMEM);

    cnorm_kernel <<<NE / 8, 256>>>(cb);
    dist_kernel  <<<NTOK / TM, 256, P1_SMEM>>>(z, cb);
    argmin_kernel<<<NTOK / 32, 256>>>(z, cb, out);
    gather_kernel<<<NTOK / GTOK, 256>>>(z, cb, out);
    finalize_kernel<<<1, 256>>>(out);
}

// round 10
// speedup vs baseline: 4.0124x; 1.1252x over previous
#include <cuda_runtime.h>
#include <cuda_fp16.h>
#include <cstdint>

// Problem constants
#define B_    16
#define CC    256
#define HW    4096
#define NTOK  65536
#define NE    1024
#define D     256
#define ZQ_ELEMS (NTOK * CC)
#define LOSS_OFF ZQ_ELEMS
#define CLS_OFF  (ZQ_ELEMS + 1)
#define IDX_OFF  (ZQ_ELEMS + 2)
#define GRID_C 2048

#define MARGIN 1.0f      // > 2x worst-case fp16 screening error; validated R8
#define KCAND  64        // per-token candidate cap (expected ~18)

// Pass-1 tiling: CTA = 128 tokens x NE codes, j-tiles of 64, k-chunks of 64
#define TM   128
#define JT   64
#define KC   64
#define NCHUNK 64            // 16 j-tiles * 4 k-chunks

// Pass-1 smem layout (bytes)
#define AS_PITCH_H 264       // halves per token row (256 + 8 pad)
#define AS_PITCH_U 132
#define OFF_AS 0             // half As[128][264] = 67584
#define BS_PITCH_U 36        // uint (half2) per code row (32 + 4 pad)
#define BS_SZ  9216          // 64 * 36 * 4
#define OFF_BS 67584         // two stages
#define OFF_CN (67584 + 2 * BS_SZ)     // 86016
#define OFF_CNT (OFF_CN + 4096)        // 90112 : int cnt[128]
#define OFF_CAND (OFF_CNT + 512)       // 90624 : ushort cand[128][KCAND]
#define P1_SMEM (OFF_CAND + TM * KCAND * 2)   // 107008

// Scratch (static device arrays are the sanctioned workaround)
__device__ int            g_cnt[NTOK];
__device__ unsigned short g_cand[(size_t)NTOK * KCAND];   // 8 MB
__device__ int            g_idx[NTOK];
__device__ float          g_cnorm[NE];
__device__ float          g_partial[GRID_C];

// ---------------------------------------------------------------------------
// helpers
// ---------------------------------------------------------------------------
__device__ __forceinline__ uint32_t pack_h2(float x, float y) {
    __half2 h = __floats2half2_rn(x, y);
    return *reinterpret_cast<uint32_t*>(&h);
}
__device__ __forceinline__ void mma_h16(float& d0, float& d1, float& d2, float& d3,
                                        uint32_t a0, uint32_t a1, uint32_t a2, uint32_t a3,
                                        uint32_t b0, uint32_t b1) {
    asm volatile(
        "mma.sync.aligned.m16n8k16.row.col.f32.f16.f16.f32 "
        "{%0,%1,%2,%3}, {%4,%5,%6,%7}, {%8,%9}, {%0,%1,%2,%3};\n"
        : "+f"(d0), "+f"(d1), "+f"(d2), "+f"(d3)
        : "r"(a0), "r"(a1), "r"(a2), "r"(a3), "r"(b0), "r"(b1));
}

// ---------------------------------------------------------------------------
// Kernel 1: per-code squared norms (warp per row)
// ---------------------------------------------------------------------------
__global__ void __launch_bounds__(256) cnorm_kernel(const float* __restrict__ cb) {
    int row  = blockIdx.x * 8 + (threadIdx.x >> 5);
    int lane = threadIdx.x & 31;
    const float* p = cb + (size_t)row * D;
    float s = 0.f;
    for (int k = lane; k < D; k += 32) { float v = p[k]; s = fmaf(v, v, s); }
    #pragma unroll
    for (int o = 16; o; o >>= 1) s += __shfl_xor_sync(0xffffffffu, s, o);
    if (lane == 0) g_cnorm[row] = s;
}

// ---------------------------------------------------------------------------
// Kernel 2 (pass 1): fp16 HMMA screening + fused candidate selection.
// Per j-tile end: running per-token approx min (quad shuffle reduce) and
// candidate push (v < runningMin + MARGIN) into smem lists. No dist matrix.
// Threshold is >= R8's global-min threshold at every tile -> candidate
// superset of R8's (which contained the true argmin with zero flips).
// ---------------------------------------------------------------------------
__global__ void __launch_bounds__(256, 2) dist_kernel(const float* __restrict__ z,
                                                      const float* __restrict__ cb) {
    extern __shared__ char smem[];
    __half*         As_h  = (__half*)(smem + OFF_AS);
    uint32_t*       As_u  = (uint32_t*)(smem + OFF_AS);
    float*          cnS   = (float*)(smem + OFF_CN);
    int*            sCnt  = (int*)(smem + OFF_CNT);
    unsigned short* sCand = (unsigned short*)(smem + OFF_CAND);

    const int tid  = threadIdx.x;
    const int w    = tid >> 5;
    const int lane = tid & 31;
    const int r    = lane >> 2;      // row-in-frag 0..7
    const int q    = lane & 3;       // quad column 0..3

    const int n0  = blockIdx.x * TM;
    const int b   = n0 >> 12;
    const int rem = n0 & (HW - 1);

    // Stage A: z[b, k, rem+t] -> half As[t][k]  (coalesced loads over t)
    for (int i = tid; i < D * TM / 4; i += 256) {
        int k  = i >> 5;
        int t4 = (i & 31) * 4;
        float4 v = *(const float4*)(z + (size_t)b * CC * HW + (size_t)k * HW + rem + t4);
        As_h[(t4 + 0) * AS_PITCH_H + k] = __float2half_rn(v.x);
        As_h[(t4 + 1) * AS_PITCH_H + k] = __float2half_rn(v.y);
        As_h[(t4 + 2) * AS_PITCH_H + k] = __float2half_rn(v.z);
        As_h[(t4 + 3) * AS_PITCH_H + k] = __float2half_rn(v.w);
    }
    for (int i = tid; i < NE; i += 256) cnS[i] = g_cnorm[i];
    for (int i = tid; i < TM; i += 256) sCnt[i] = 0;

    // B staging task: thread -> (n = tid>>2, kq = tid&3), 16 floats
    const int bn  = tid >> 2;
    const int bkq = tid & 3;

    // prefetch chunk 0
    float4 pf[4];
    {
        const float* src = cb + (size_t)bn * D + bkq * 16;
        #pragma unroll
        for (int u = 0; u < 4; u++) pf[u] = *(const float4*)(src + u * 4);
        uint32_t* Bs = (uint32_t*)(smem + OFF_BS);
        #pragma unroll
        for (int u = 0; u < 4; u++) {
            Bs[bn * BS_PITCH_U + bkq * 8 + u * 2 + 0] = pack_h2(-2.f * pf[u].x, -2.f * pf[u].y);
            Bs[bn * BS_PITCH_U + bkq * 8 + u * 2 + 1] = pack_h2(-2.f * pf[u].z, -2.f * pf[u].w);
        }
    }
    __syncthreads();

    float acc[8][4];
    #pragma unroll
    for (int nt = 0; nt < 8; nt++)
        #pragma unroll
        for (int c = 0; c < 4; c++) acc[nt][c] = 0.f;

    const int t0 = w * 16;
    const int tA = t0 + r;         // local token owned via acc[.][0..1]
    const int tB = tA + 8;         // local token owned via acc[.][2..3]
    float curMin0 = 3.4e38f, curMin1 = 3.4e38f;

    for (int g = 0; g < NCHUNK; g++) {
        const int jt = g >> 2;
        const int kc = g & 3;

        // prefetch next chunk's B from global
        if (g + 1 < NCHUNK) {
            const int j0n = ((g + 1) >> 2) * JT;
            const int kbn = ((g + 1) & 3) * KC;
            const float* src = cb + (size_t)(j0n + bn) * D + kbn + bkq * 16;
            #pragma unroll
            for (int u = 0; u < 4; u++) pf[u] = *(const float4*)(src + u * 4);
        }

        // compute chunk g from stage g&1
        const uint32_t* Bs = (const uint32_t*)(smem + OFF_BS + (g & 1) * BS_SZ);
        #pragma unroll
        for (int s = 0; s < 4; s++) {
            const int ah_base = (t0 + r) * AS_PITCH_U + kc * 32 + s * 8 + q;
            uint32_t a0 = As_u[ah_base];
            uint32_t a1 = As_u[ah_base + 8 * AS_PITCH_U];
            uint32_t a2 = As_u[ah_base + 4];
            uint32_t a3 = As_u[ah_base + 8 * AS_PITCH_U + 4];
            #pragma unroll
            for (int nt = 0; nt < 8; nt++) {
                const int jn = nt * 8 + (lane >> 2);
                uint32_t b0 = Bs[jn * BS_PITCH_U + s * 8 + q];
                uint32_t b1 = Bs[jn * BS_PITCH_U + s * 8 + q + 4];
                mma_h16(acc[nt][0], acc[nt][1], acc[nt][2], acc[nt][3],
                        a0, a1, a2, a3, b0, b1);
            }
        }

        // store next chunk into the other stage
        if (g + 1 < NCHUNK) {
            uint32_t* Bs2 = (uint32_t*)(smem + OFF_BS + ((g + 1) & 1) * BS_SZ);
            #pragma unroll
            for (int u = 0; u < 4; u++) {
                Bs2[bn * BS_PITCH_U + bkq * 8 + u * 2 + 0] = pack_h2(-2.f * pf[u].x, -2.f * pf[u].y);
                Bs2[bn * BS_PITCH_U + bkq * 8 + u * 2 + 1] = pack_h2(-2.f * pf[u].z, -2.f * pf[u].w);
            }
        }
        __syncthreads();

        // end of j-tile: running-min update + candidate pushes
        if (kc == 3) {
            const int jbase = jt * JT + 2 * q;
            float mn0 = 3.4e38f, mn1 = 3.4e38f;
            #pragma unroll
            for (int nt = 0; nt < 8; nt++) {
                int j = jbase + nt * 8;
                float c0 = cnS[j], c1 = cnS[j + 1];
                mn0 = fminf(mn0, fminf(c0 + acc[nt][0], c1 + acc[nt][1]));
                mn1 = fminf(mn1, fminf(c0 + acc[nt][2], c1 + acc[nt][3]));
            }
            // quad reduce (lanes r*4 .. r*4+3 are consecutive)
            mn0 = fminf(mn0, __shfl_xor_sync(0xffffffffu, mn0, 1));
            mn0 = fminf(mn0, __shfl_xor_sync(0xffffffffu, mn0, 2));
            mn1 = fminf(mn1, __shfl_xor_sync(0xffffffffu, mn1, 1));
            mn1 = fminf(mn1, __shfl_xor_sync(0xffffffffu, mn1, 2));
            curMin0 = fminf(curMin0, mn0);
            curMin1 = fminf(curMin1, mn1);
            const float thr0 = curMin0 + MARGIN;
            const float thr1 = curMin1 + MARGIN;
            #pragma unroll
            for (int nt = 0; nt < 8; nt++) {
                int j = jbase + nt * 8;
                float c0 = cnS[j], c1 = cnS[j + 1];
                if (c0 + acc[nt][0] < thr0) {
                    int pos = atomicAdd(&sCnt[tA], 1);
                    if (pos < KCAND) sCand[tA * KCAND + pos] = (unsigned short)j;
                }
                if (c1 + acc[nt][1] < thr0) {
                    int pos = atomicAdd(&sCnt[tA], 1);
                    if (pos < KCAND) sCand[tA * KCAND + pos] = (unsigned short)(j + 1);
                }
                if (c0 + acc[nt][2] < thr1) {
                    int pos = atomicAdd(&sCnt[tB], 1);
                    if (pos < KCAND) sCand[tB * KCAND + pos] = (unsigned short)j;
                }
                if (c1 + acc[nt][3] < thr1) {
                    int pos = atomicAdd(&sCnt[tB], 1);
                    if (pos < KCAND) sCand[tB * KCAND + pos] = (unsigned short)(j + 1);
                }
                acc[nt][0] = acc[nt][1] = acc[nt][2] = acc[nt][3] = 0.f;
            }
        }
    }

    // write lists to global (coalesced)
    __syncthreads();
    for (int i = tid; i < TM; i += 256) g_cnt[n0 + i] = sCnt[i];
    {
        const uint32_t* cu = (const uint32_t*)sCand;                 // [128][KCAND/2]
        uint32_t* gu = (uint32_t*)g_cand + (size_t)n0 * (KCAND / 2);
        for (int i = tid; i < TM * (KCAND / 2); i += 256) gu[i] = cu[i];
    }
}

// ---------------------------------------------------------------------------
// Kernel 3 (pass 2): exact argmin over candidate lists (fp32 rescore).
// Block = 32 tokens; warp = 4 tokens. Lists unsorted -> full comparator.
// Overflowed tokens (cnt > KCAND) fall back to exact full scan.
// ---------------------------------------------------------------------------
__global__ void __launch_bounds__(256) argmin_kernel(const float* __restrict__ z,
                                                     const float* __restrict__ cb,
                                                     float* __restrict__ dout) {
    __shared__ float zs[32][260];
    const int tid  = threadIdx.x;
    const int w    = tid >> 5;
    const int lane = tid & 31;

    const int n0  = blockIdx.x * 32;
    const int b   = n0 >> 12;
    const int hw0 = n0 & (HW - 1);

    // stage z tile [t][k]
    for (int i = tid; i < D * 32 / 4; i += 256) {
        int k  = i >> 3;
        int t4 = (i & 7) * 4;
        float4 v = *(const float4*)(z + (size_t)b * CC * HW + (size_t)k * HW + hw0 + t4);
        zs[t4 + 0][k] = v.x; zs[t4 + 1][k] = v.y;
        zs[t4 + 2][k] = v.z; zs[t4 + 3][k] = v.w;
    }
    __syncthreads();

    for (int tt = 0; tt < 4; tt++) {
        const int t = w * 4 + tt;
        const int n = n0 + t;
        const int cnt = g_cnt[n];

        float best = 3.4e38f;
        int   bi   = 0;
        if (cnt <= KCAND) {
            const unsigned short* lst = g_cand + (size_t)n * KCAND;
            for (int ci = 0; ci < cnt; ci++) {
                int j = lst[ci];
                const float* crow = cb + (size_t)j * D;
                float s = 0.f;
                #pragma unroll
                for (int u = 0; u < 8; u++)
                    s = fmaf(zs[t][lane + 32 * u], crow[lane + 32 * u], s);
                #pragma unroll
                for (int o = 16; o; o >>= 1) s += __shfl_xor_sync(0xffffffffu, s, o);
                float dist = g_cnorm[j] - 2.0f * s;
                if (dist < best || (dist == best && j < bi)) { best = dist; bi = j; }
            }
        } else {
            // exact full scan (rare overflow fallback); ascending j, strict <
            for (int j = 0; j < NE; j++) {
                const float* crow = cb + (size_t)j * D;
                float s = 0.f;
                #pragma unroll
                for (int u = 0; u < 8; u++)
                    s = fmaf(zs[t][lane + 32 * u], crow[lane + 32 * u], s);
                #pragma unroll
                for (int o = 16; o; o >>= 1) s += __shfl_xor_sync(0xffffffffu, s, o);
                float dist = g_cnorm[j] - 2.0f * s;
                if (dist < best) { best = dist; bi = j; }
            }
        }
        if (lane == 0) {
            g_idx[n] = bi;
            dout[IDX_OFF + n] = (float)bi;
        }
    }
}

// ---------------------------------------------------------------------------
// Kernel 4: gather z_q + straight-through output + partial loss
// ---------------------------------------------------------------------------
#define GTOK 32
__global__ void __launch_bounds__(256) gather_kernel(const float* __restrict__ z,
                                                     const float* __restrict__ cb,
                                                     float* __restrict__ dout) {
    __shared__ float zq[GTOK][257];
    __shared__ int   idxs[GTOK];
    __shared__ float ws[8];

    const int tid = threadIdx.x;
    const int n0  = blockIdx.x * GTOK;
    const int b   = n0 / HW;
    const int hw0 = n0 % HW;

    if (tid < GTOK) idxs[tid] = g_idx[n0 + tid];
    __syncthreads();

    #pragma unroll 4
    for (int t = 0; t < GTOK; t++) {
        zq[t][tid] = cb[(size_t)idxs[t] * D + tid];
    }
    __syncthreads();

    const int t  = tid & 31;
    const int c0 = tid >> 5;
    float s = 0.f;
    const float* zb = z    + (size_t)b * CC * HW + hw0 + t;
    float*       ob = dout + (size_t)b * CC * HW + hw0 + t;
    #pragma unroll 8
    for (int it = 0; it < 32; it++) {
        int c = c0 * 32 + it;
        float zv = zb[(size_t)c * HW];
        float d  = zq[t][c] - zv;
        ob[(size_t)c * HW] = zv + d;   // z + sg(z_q - z), exact fp32 expr
        s = fmaf(d, d, s);
    }

    #pragma unroll
    for (int o = 16; o; o >>= 1) s += __shfl_xor_sync(0xffffffffu, s, o);
    if ((tid & 31) == 0) ws[tid >> 5] = s;
    __syncthreads();
    if (tid < 8) {
        float v = ws[tid];
        #pragma unroll
        for (int o = 4; o; o >>= 1) v += __shfl_xor_sync(0xffu, v, o);
        if (tid == 0) g_partial[blockIdx.x] = v;
    }
}

// ---------------------------------------------------------------------------
// Kernel 5: deterministic final reduction
// ---------------------------------------------------------------------------
__global__ void __launch_bounds__(256) finalize_kernel(float* __restrict__ dout) {
    __shared__ float sh[256];
    float s = 0.f;
    for (int i = threadIdx.x; i < GRID_C; i += 256) s += g_partial[i];
    sh[threadIdx.x] = s;
    __syncthreads();
    for (int o = 128; o; o >>= 1) {
        if (threadIdx.x < o) sh[threadIdx.x] += sh[threadIdx.x + o];
        __syncthreads();
    }
    if (threadIdx.x == 0) {
        dout[LOSS_OFF] = sh[0] * (2.0f / (float)ZQ_ELEMS);
        dout[CLS_OFF]  = 0.0f;
    }
}

// ---------------------------------------------------------------------------
extern "C" void kernel_launch(void* const* d_in, const int* in_sizes, int n_in,
                              void* d_out, int out_size) {
    const float* z  = (const float*)d_in[0];   // [B,C,H,W] fp32
    const float* cb = (const float*)d_in[1];   // [NE, D]   fp32
    float* out = (float*)d_out;

    cudaFuncSetAttribute(dist_kernel,
                         cudaFuncAttributeMaxDynamicSharedMemorySize, P1_SMEM);

    cnorm_kernel <<<NE / 8, 256>>>(cb);
    dist_kernel  <<<NTOK / TM, 256, P1_SMEM>>>(z, cb);
    argmin_kernel<<<NTOK / 32, 256>>>(z, cb, out);
    gather_kernel<<<NTOK / GTOK, 256>>>(z, cb, out);
    finalize_kernel<<<1, 256>>>(out);
}